// round 11
// baseline (speedup 1.0000x reference)
#include <cuda_runtime.h>

// CubicShapeFunction: 500K points, 4^3 cubic B-spline stencil.
// Output layout (flat float32):
//   [0, N*64)             shapef [N,64]
//   [N*64, N*64+N*192)    grad   [N,64,3]
//
// R10: exact R5 structure (best known, 71.7us) with default write-back stores
// instead of .cs streaming — lets L2 batch dirty-line drains for better DRAM
// row locality on the pure-write stream. Everything else unchanged.

constexpr int   N_POINTS      = 500000;
constexpr float INV_CELL      = 20.0f;
constexpr int   PTS_PER_BLOCK = 16;     // 8 warps x 2 points; 500000 % 16 == 0
constexpr int   THREADS       = 256;

__global__ __launch_bounds__(THREADS, 8)
void cubic_shape_kernel(const float* __restrict__ pos, float* __restrict__ out) {
    __shared__ float  s_b [PTS_PER_BLOCK][3][4];   // basis
    __shared__ float  s_db[PTS_PER_BLOCK][3][4];   // d(basis)*INV_CELL
    __shared__ float4 s_gr[PTS_PER_BLOCK * 48];    // 768 float4 = 12 KB grad staging

    const int tid  = threadIdx.x;
    const int wid  = tid >> 5;          // warp id: owns points {2w, 2w+1}
    const int lane = tid & 31;
    const int pt0  = blockIdx.x * PTS_PER_BLOCK;

    // ---- Phase 1 (warp-local): 24 lanes build spline table for 2 points ----
    if (lane < 24) {
        const int p    = lane / 12;          // 0 or 1 within warp
        const int r    = lane % 12;
        const int axis = r >> 2;
        const int o    = r & 3;
        const int pl   = wid * 2 + p;        // point index within block

        const float pp   = pos[(pt0 + pl) * 3 + axis];
        const float rel  = pp * INV_CELL;                 // ORIGIN = 0
        const float base = floorf(rel) - 1.0f;
        const float x    = rel - (base + (float)o);       // matches reference expr

        float bb, dd;
        if (o == 0) {            // x in [1,2): c4 branch
            bb = (((-1.0f/6.0f) * x + 1.0f) * x - 2.0f) * x + 4.0f/3.0f;
            dd = (-0.5f * x + 2.0f) * x - 2.0f;
        } else if (o == 1) {     // x in [0,1): c3 branch
            bb = (0.5f * x - 1.0f) * x * x + 2.0f/3.0f;
            dd = (1.5f * x - 2.0f) * x;
        } else if (o == 2) {     // x in [-1,0): c2 branch
            bb = (-0.5f * x - 1.0f) * x * x + 2.0f/3.0f;
            dd = (-1.5f * x - 2.0f) * x;
        } else {                 // x in [-2,-1): c1 branch
            bb = (((1.0f/6.0f) * x + 1.0f) * x + 2.0f) * x + 4.0f/3.0f;
            dd = (0.5f * x + 2.0f) * x + 2.0f;
        }
        s_b [pl][axis][o] = bb;
        s_db[pl][axis][o] = INV_CELL * dd;
    }
    __syncwarp();

    // ---- Phase 2 (warp-local): lane = (point-in-warp, i, j); k vectorized ----
    {
        const int pl = wid * 2 + (lane >> 4);   // point within block
        const int ij = lane & 15;
        const int i  = ij >> 2;
        const int j  = ij & 3;

        const float bx  = s_b [pl][0][i];
        const float by  = s_b [pl][1][j];
        const float dbx = s_db[pl][0][i];
        const float dby = s_db[pl][1][j];
        const float4 bz  = *(const float4*)s_b [pl][2];
        const float4 dbz = *(const float4*)s_db[pl][2];

        const float bxy   = bx * by;
        const float dbx_y = dbx * by;
        const float dby_x = dby * bx;

        // shapef: consecutive tid -> consecutive float4, fully coalesced
        const float4 sf = make_float4(bxy * bz.x, bxy * bz.y, bxy * bz.z, bxy * bz.w);
        float4* osf = (float4*)out;
        osf[(size_t)pt0 * 16 + tid] = sf;

        // grad entry k: ( dbx*by*bz[k], dby*bx*bz[k], dbz[k]*bx*by )
        float4 g0 = make_float4(dbx_y * bz.x, dby_x * bz.x, dbz.x * bxy,
                                dbx_y * bz.y);
        float4 g1 = make_float4(dby_x * bz.y, dbz.y * bxy,
                                dbx_y * bz.z, dby_x * bz.z);
        float4 g2 = make_float4(dbz.z * bxy,
                                dbx_y * bz.w, dby_x * bz.w, dbz.w * bxy);

        // stage grad (stride-3 float4 across lanes: conflict-free per phase)
        float4* g = &s_gr[(pl * 16 + ij) * 3];
        g[0] = g0;
        g[1] = g1;
        g[2] = g2;
    }
    __syncwarp();

    // ---- Phase 3 (warp-local): drain this warp's 96 float4, coalesced ----
    {
        float4* ogr = (float4*)(out + (size_t)N_POINTS * 64)
                    + (size_t)blockIdx.x * (PTS_PER_BLOCK * 48);
        const int base = wid * 96;
        #pragma unroll
        for (int r = 0; r < 3; r++) {
            const int idx = base + r * 32 + lane;
            ogr[idx] = s_gr[idx];
        }
    }
}

extern "C" void kernel_launch(void* const* d_in, const int* in_sizes, int n_in,
                              void* d_out, int out_size) {
    const float* pos = (const float*)d_in[0];
    float* out = (float*)d_out;
    cubic_shape_kernel<<<N_POINTS / PTS_PER_BLOCK, THREADS>>>(pos, out);
}

// round 12
// speedup vs baseline: 1.4346x; 1.4346x over previous
#include <cuda_runtime.h>

// CubicShapeFunction: 500K points, 4^3 cubic B-spline stencil.
// Output layout (flat float32):
//   [0, N*64)             shapef [N,64]
//   [N*64, N*64+N*192)    grad   [N,64,3]
//
// FINAL (= R5, best known 71.7us = ~7.1 TB/s effective write BW, ~89% of HBM):
// warp-synchronous, 2 points per warp, spline table built once per point in
// SMEM, grad transposed through SMEM so every global store is a coalesced
// minimal-wavefront STG.128, all stores .cs streaming (write-back and v8
// variants both measured slower; this is the DRAM-write floor).

constexpr int   N_POINTS      = 500000;
constexpr float INV_CELL      = 20.0f;
constexpr int   PTS_PER_BLOCK = 16;     // 8 warps x 2 points; 500000 % 16 == 0
constexpr int   THREADS       = 256;

__global__ __launch_bounds__(THREADS, 8)
void cubic_shape_kernel(const float* __restrict__ pos, float* __restrict__ out) {
    __shared__ float  s_b [PTS_PER_BLOCK][3][4];   // basis
    __shared__ float  s_db[PTS_PER_BLOCK][3][4];   // d(basis)*INV_CELL
    __shared__ float4 s_gr[PTS_PER_BLOCK * 48];    // 768 float4 = 12 KB grad staging

    const int tid  = threadIdx.x;
    const int wid  = tid >> 5;          // warp id: owns points {2w, 2w+1}
    const int lane = tid & 31;
    const int pt0  = blockIdx.x * PTS_PER_BLOCK;

    // ---- Phase 1 (warp-local): 24 lanes build spline table for 2 points ----
    if (lane < 24) {
        const int p    = lane / 12;          // 0 or 1 within warp
        const int r    = lane % 12;
        const int axis = r >> 2;
        const int o    = r & 3;
        const int pl   = wid * 2 + p;        // point index within block

        const float pp   = pos[(pt0 + pl) * 3 + axis];
        const float rel  = pp * INV_CELL;                 // ORIGIN = 0
        const float base = floorf(rel) - 1.0f;
        const float x    = rel - (base + (float)o);       // matches reference expr

        float bb, dd;
        if (o == 0) {            // x in [1,2): c4 branch
            bb = (((-1.0f/6.0f) * x + 1.0f) * x - 2.0f) * x + 4.0f/3.0f;
            dd = (-0.5f * x + 2.0f) * x - 2.0f;
        } else if (o == 1) {     // x in [0,1): c3 branch
            bb = (0.5f * x - 1.0f) * x * x + 2.0f/3.0f;
            dd = (1.5f * x - 2.0f) * x;
        } else if (o == 2) {     // x in [-1,0): c2 branch
            bb = (-0.5f * x - 1.0f) * x * x + 2.0f/3.0f;
            dd = (-1.5f * x - 2.0f) * x;
        } else {                 // x in [-2,-1): c1 branch
            bb = (((1.0f/6.0f) * x + 1.0f) * x + 2.0f) * x + 4.0f/3.0f;
            dd = (0.5f * x + 2.0f) * x + 2.0f;
        }
        s_b [pl][axis][o] = bb;
        s_db[pl][axis][o] = INV_CELL * dd;
    }
    __syncwarp();

    // ---- Phase 2 (warp-local): lane = (point-in-warp, i, j); k vectorized ----
    {
        const int pl = wid * 2 + (lane >> 4);   // point within block
        const int ij = lane & 15;
        const int i  = ij >> 2;
        const int j  = ij & 3;

        const float bx  = s_b [pl][0][i];
        const float by  = s_b [pl][1][j];
        const float dbx = s_db[pl][0][i];
        const float dby = s_db[pl][1][j];
        const float4 bz  = *(const float4*)s_b [pl][2];
        const float4 dbz = *(const float4*)s_db[pl][2];

        const float bxy   = bx * by;
        const float dbx_y = dbx * by;
        const float dby_x = dby * bx;

        // shapef: consecutive tid -> consecutive float4, fully coalesced
        const float4 sf = make_float4(bxy * bz.x, bxy * bz.y, bxy * bz.z, bxy * bz.w);
        float4* osf = (float4*)out;
        __stcs(&osf[(size_t)pt0 * 16 + tid], sf);

        // grad entry k: ( dbx*by*bz[k], dby*bx*bz[k], dbz[k]*bx*by )
        float4 g0 = make_float4(dbx_y * bz.x, dby_x * bz.x, dbz.x * bxy,
                                dbx_y * bz.y);
        float4 g1 = make_float4(dby_x * bz.y, dbz.y * bxy,
                                dbx_y * bz.z, dby_x * bz.z);
        float4 g2 = make_float4(dbz.z * bxy,
                                dbx_y * bz.w, dby_x * bz.w, dbz.w * bxy);

        // stage grad (stride-3 float4 across lanes: conflict-free per phase)
        float4* g = &s_gr[(pl * 16 + ij) * 3];
        g[0] = g0;
        g[1] = g1;
        g[2] = g2;
    }
    __syncwarp();

    // ---- Phase 3 (warp-local): drain this warp's 96 float4, coalesced ----
    {
        float4* ogr = (float4*)(out + (size_t)N_POINTS * 64)
                    + (size_t)blockIdx.x * (PTS_PER_BLOCK * 48);
        const int base = wid * 96;
        #pragma unroll
        for (int r = 0; r < 3; r++) {
            const int idx = base + r * 32 + lane;
            __stcs(&ogr[idx], s_gr[idx]);
        }
    }
}

extern "C" void kernel_launch(void* const* d_in, const int* in_sizes, int n_in,
                              void* d_out, int out_size) {
    const float* pos = (const float*)d_in[0];
    float* out = (float*)d_out;
    cubic_shape_kernel<<<N_POINTS / PTS_PER_BLOCK, THREADS>>>(pos, out);
}